// round 2
// baseline (speedup 1.0000x reference)
#include <cuda_runtime.h>

// N = 2^26 FFT of real fp32 input -> stacked [2, N] (re, im) fp32.
// Stockham, radix-16 in registers, 7 global passes: 16^6 * 4 = 2^26.
//   P1: s=1     radix-16, real-input load, smem-transposed store
//   P2: s=16    radix-16, smem-transposed store
//   P3..P6: s=256,4096,65536,2^20 radix-16, direct coalesced store
//   P7: s=2^24  radix-4, twiddle-free, planar split-store to d_out

#define NFFT (1u << 26)
#define N16  (NFFT >> 4)
#define N4   (NFFT >> 2)

static __device__ float2 g_buf[NFFT];  // 512 MB scratch (sanctioned)

__device__ __forceinline__ float2 cmul(float2 a, float2 b) {
    return make_float2(a.x * b.x - a.y * b.y, a.x * b.y + a.y * b.x);
}
__device__ __forceinline__ float2 cadd(float2 a, float2 b) {
    return make_float2(a.x + b.x, a.y + b.y);
}
__device__ __forceinline__ float2 csub(float2 a, float2 b) {
    return make_float2(a.x - b.x, a.y - b.y);
}
// multiply by -i: -i*(x+iy) = y - i x
__device__ __forceinline__ float2 cmul_negi(float2 a) { return make_float2(a.y, -a.x); }
// multiply by +i
__device__ __forceinline__ float2 cmul_posi(float2 a) { return make_float2(-a.y, a.x); }

// In-place forward DFT-16 on a[0..15] (natural order in, natural order out).
// Decomposition r = r1 + 4*r2, output A[k1 + 4*k2]:
//   b[r1][k1] = DFT4_{r2}( a[r1 + 4 r2] )
//   c[r1][k1] = b[r1][k1] * exp(-2 pi i r1 k1 / 16)
//   A[k1+4k2] = DFT4_{r1}( c[r1][k1] )
__device__ __forceinline__ void dft16(float2 a[16]) {
    const float C1 = 0.92387953251128675613f;  // cos(pi/8)
    const float S1 = 0.38268343236508977173f;  // sin(pi/8)
    const float H  = 0.70710678118654752440f;  // sqrt(2)/2
    const float2 W1 = make_float2( C1, -S1);
    const float2 W2 = make_float2(  H,  -H);
    const float2 W3 = make_float2( S1, -C1);
    const float2 W4 = make_float2(0.f, -1.f);
    const float2 W6 = make_float2( -H,  -H);
    const float2 W9 = make_float2(-C1,  S1);

    float2 b[16];  // b[r1*4 + k1]
#pragma unroll
    for (int r1 = 0; r1 < 4; ++r1) {
        float2 x0 = a[r1], x1 = a[r1 + 4], x2 = a[r1 + 8], x3 = a[r1 + 12];
        float2 e = cadd(x0, x2), f = csub(x0, x2);
        float2 g = cadd(x1, x3), h = csub(x1, x3);
        b[r1 * 4 + 0] = cadd(e, g);
        b[r1 * 4 + 1] = cadd(f, cmul_negi(h));
        b[r1 * 4 + 2] = csub(e, g);
        b[r1 * 4 + 3] = cadd(f, cmul_posi(h));
    }
    // twiddles exp(-2 pi i r1 k1/16)
    b[5]  = cmul(b[5],  W1);
    b[6]  = cmul(b[6],  W2);
    b[7]  = cmul(b[7],  W3);
    b[9]  = cmul(b[9],  W2);
    b[10] = cmul(b[10], W4);
    b[11] = cmul(b[11], W6);
    b[13] = cmul(b[13], W3);
    b[14] = cmul(b[14], W6);
    b[15] = cmul(b[15], W9);
#pragma unroll
    for (int k1 = 0; k1 < 4; ++k1) {
        float2 x0 = b[k1], x1 = b[4 + k1], x2 = b[8 + k1], x3 = b[12 + k1];
        float2 e = cadd(x0, x2), f = csub(x0, x2);
        float2 g = cadd(x1, x3), h = csub(x1, x3);
        a[k1 + 0]  = cadd(e, g);
        a[k1 + 4]  = cadd(f, cmul_negi(h));
        a[k1 + 8]  = csub(e, g);
        a[k1 + 12] = cadd(f, cmul_posi(h));
    }
}

#define TPB 256u
#define TWO_PI 6.28318530717958647692f

// ------------------------- P1: s = 1, real input -------------------------
__global__ void fft_p1_real(const float* __restrict__ x, float2* __restrict__ y) {
    __shared__ float2 sm[4352];  // 4096 + 256 skew pad
    unsigned tid = threadIdx.x;
    unsigned t = blockIdx.x * TPB + tid;
    float2 a[16];
#pragma unroll
    for (int r = 0; r < 16; ++r) a[r] = make_float2(x[t + (unsigned)r * N16], 0.0f);
    dft16(a);
    float th = -TWO_PI * (float)t / (float)NFFT;  // |th| < 2pi/16
    float sn, cs;
    __sincosf(th, &sn, &cs);
    float2 w1 = make_float2(cs, sn);
    float2 w = make_float2(1.0f, 0.0f);
#pragma unroll
    for (int k = 0; k < 16; ++k) {
        unsigned l = 16u * tid + (unsigned)k;  // local output index (y[16 t + k])
        sm[l + (l >> 4)] = cmul(a[k], w);
        w = cmul(w, w1);
    }
    __syncthreads();
    unsigned base = blockIdx.x * 4096u;
#pragma unroll
    for (int it = 0; it < 16; ++it) {
        unsigned j = tid + (unsigned)it * TPB;
        y[base + j] = sm[j + (j >> 4)];
    }
}

// ------------------------- P2: s = 16 -------------------------
__global__ void fft_p2_s16(const float2* __restrict__ x, float2* __restrict__ y) {
    __shared__ float2 sm[4352];
    unsigned tid = threadIdx.x;
    unsigned t = blockIdx.x * TPB + tid;
    float2 a[16];
#pragma unroll
    for (int r = 0; r < 16; ++r) a[r] = x[t + (unsigned)r * N16];
    dft16(a);
    unsigned q = tid & 15u;          // t & 15 (block base is multiple of 256)
    unsigned pp = tid >> 4;          // p - p0, in [0,16)
    unsigned ps = t - (t & 15u);     // p * s
    float th = -TWO_PI * (float)ps / (float)NFFT;
    float sn, cs;
    __sincosf(th, &sn, &cs);
    float2 w1 = make_float2(cs, sn);
    float2 w = make_float2(1.0f, 0.0f);
#pragma unroll
    for (int k = 0; k < 16; ++k) {
        // global idx = q + 256 p + 16 k; local = q + 16 k + 256 (p - p0)
        unsigned l = q + 16u * (unsigned)k + 256u * pp;
        sm[l + (l >> 4)] = cmul(a[k], w);
        w = cmul(w, w1);
    }
    __syncthreads();
    unsigned base = blockIdx.x * 4096u;
#pragma unroll
    for (int it = 0; it < 16; ++it) {
        unsigned j = tid + (unsigned)it * TPB;
        y[base + j] = sm[j + (j >> 4)];
    }
}

// ------------------- P3..P6: generic radix-16, s >= 32 -------------------
__global__ void fft_p16(const float2* __restrict__ x, float2* __restrict__ y,
                        int log2s) {
    unsigned t = blockIdx.x * TPB + threadIdx.x;
    unsigned s = 1u << log2s;
    unsigned q = t & (s - 1u);
    unsigned ps = t - q;  // p * s  (< N/16, exact in float)
    float2 a[16];
#pragma unroll
    for (int r = 0; r < 16; ++r) a[r] = x[t + (unsigned)r * N16];
    dft16(a);
    float th = -TWO_PI * (float)ps / (float)NFFT;
    float sn, cs;
    __sincosf(th, &sn, &cs);
    float2 w1 = make_float2(cs, sn);
    unsigned base = q + (ps << 4);  // q + 16 s p
    float2 w = make_float2(1.0f, 0.0f);
#pragma unroll
    for (int k = 0; k < 16; ++k) {
        y[base + ((unsigned)k << log2s)] = cmul(a[k], w);
        w = cmul(w, w1);
    }
}

// --------------- P7: radix-4, s = N/4, planar split store ---------------
__global__ void fft_p7_last(const float2* __restrict__ x, float* __restrict__ out) {
    unsigned t = blockIdx.x * TPB + threadIdx.x;
    float2 x0 = x[t];
    float2 x1 = x[t + N4];
    float2 x2 = x[t + 2 * N4];
    float2 x3 = x[t + 3 * N4];
    float2 e = cadd(x0, x2), f = csub(x0, x2);
    float2 g = cadd(x1, x3), h = csub(x1, x3);
    float2 r0 = cadd(e, g);
    float2 r1 = cadd(f, cmul_negi(h));
    float2 r2 = csub(e, g);
    float2 r3 = cadd(f, cmul_posi(h));
    out[t]          = r0.x;  out[NFFT + t]          = r0.y;
    out[t + N4]     = r1.x;  out[NFFT + t + N4]     = r1.y;
    out[t + 2 * N4] = r2.x;  out[NFFT + t + 2 * N4] = r2.y;
    out[t + 3 * N4] = r3.x;  out[NFFT + t + 3 * N4] = r3.y;
}

// ---------------------------------------------------------------------------
// Schedule: P1: x -> D; P2: D -> B; P3: B -> D; P4: D -> B; P5: B -> D;
//           P6: D -> B; P7: B -> out (d_out, planar). No aliasing hazards.
// ---------------------------------------------------------------------------
extern "C" void kernel_launch(void* const* d_in, const int* in_sizes, int n_in,
                              void* d_out, int out_size) {
    const float* x = (const float*)d_in[0];
    float* out = (float*)d_out;
    float2* D = (float2*)d_out;  // NFFT float2 == out_size floats
    float2* B = nullptr;
    cudaGetSymbolAddress((void**)&B, g_buf);

    const unsigned blocks16 = N16 / TPB;  // 16384
    fft_p1_real<<<blocks16, TPB>>>(x, D);
    fft_p2_s16 <<<blocks16, TPB>>>(D, B);
    fft_p16    <<<blocks16, TPB>>>(B, D, 8);
    fft_p16    <<<blocks16, TPB>>>(D, B, 12);
    fft_p16    <<<blocks16, TPB>>>(B, D, 16);
    fft_p16    <<<blocks16, TPB>>>(D, B, 20);
    fft_p7_last<<<N4 / TPB, TPB>>>(B, out);
}

// round 3
// speedup vs baseline: 1.6645x; 1.6645x over previous
#include <cuda_runtime.h>

// N = 2^26 FFT of real fp32 input -> stacked [2, N] (re, im) fp32.
// Stockham radix-256 (two fused radix-16 layers through smem), 4 global passes:
//   P1: s=1      radix-256, real-input load, smem-restaged contiguous store
//   P2: s=256    radix-256, direct coalesced store
//   P3: s=65536  radix-256, direct coalesced store
//   P4: s=2^24   radix-4, twiddle-free, planar split-store to d_out

#define NFFT  (1u << 26)
#define N256  (NFFT >> 8)   // 2^18 = groups per radix-256 pass
#define N4    (NFFT >> 2)
#define TPB   256u
#define TWO_PI 6.28318530717958647692f

static __device__ float2 g_buf[NFFT];  // 512 MB scratch (sanctioned)

// exp(-2*pi*i*j/256), j = 0..15
__constant__ float2 c_w256[16] = {
    { 1.00000000000000000f, -0.00000000000000000f},
    { 0.99969881869620422f, -0.02454122852291229f},
    { 0.99879545620517241f, -0.04906767432741801f},
    { 0.99729045667869021f, -0.07356456359966743f},
    { 0.99518472667219693f, -0.09801714032956060f},
    { 0.99247953459870997f, -0.12241067519921620f},
    { 0.98917650996478101f, -0.14673047445536175f},
    { 0.98527764238894122f, -0.17096188876030122f},
    { 0.98078528040323044f, -0.19509032201612825f},
    { 0.97570213003852857f, -0.21910124015686980f},
    { 0.97003125319454397f, -0.24298017990326390f},
    { 0.96377606579543984f, -0.26671275747489837f},
    { 0.95694033573220882f, -0.29028467725446233f},
    { 0.94952818059303667f, -0.31368174039889152f},
    { 0.94154406518302081f, -0.33688985339222005f},
    { 0.93299279883473896f, -0.35989503653498817f}
};

__device__ __forceinline__ float2 cmul(float2 a, float2 b) {
    return make_float2(a.x * b.x - a.y * b.y, a.x * b.y + a.y * b.x);
}
__device__ __forceinline__ float2 cadd(float2 a, float2 b) {
    return make_float2(a.x + b.x, a.y + b.y);
}
__device__ __forceinline__ float2 csub(float2 a, float2 b) {
    return make_float2(a.x - b.x, a.y - b.y);
}
__device__ __forceinline__ float2 cmul_negi(float2 a) { return make_float2(a.y, -a.x); }
__device__ __forceinline__ float2 cmul_posi(float2 a) { return make_float2(-a.y, a.x); }

// In-place forward DFT-16, natural in/out. (Verified in round-2 kernel.)
__device__ __forceinline__ void dft16(float2 a[16]) {
    const float C1 = 0.92387953251128675613f;
    const float S1 = 0.38268343236508977173f;
    const float H  = 0.70710678118654752440f;
    const float2 W1 = make_float2( C1, -S1);
    const float2 W2 = make_float2(  H,  -H);
    const float2 W3 = make_float2( S1, -C1);
    const float2 W4 = make_float2(0.f, -1.f);
    const float2 W6 = make_float2( -H,  -H);
    const float2 W9 = make_float2(-C1,  S1);

    float2 b[16];
#pragma unroll
    for (int r1 = 0; r1 < 4; ++r1) {
        float2 x0 = a[r1], x1 = a[r1 + 4], x2 = a[r1 + 8], x3 = a[r1 + 12];
        float2 e = cadd(x0, x2), f = csub(x0, x2);
        float2 g = cadd(x1, x3), h = csub(x1, x3);
        b[r1 * 4 + 0] = cadd(e, g);
        b[r1 * 4 + 1] = cadd(f, cmul_negi(h));
        b[r1 * 4 + 2] = csub(e, g);
        b[r1 * 4 + 3] = cadd(f, cmul_posi(h));
    }
    b[5]  = cmul(b[5],  W1);
    b[6]  = cmul(b[6],  W2);
    b[7]  = cmul(b[7],  W3);
    b[9]  = cmul(b[9],  W2);
    b[10] = cmul(b[10], W4);
    b[11] = cmul(b[11], W6);
    b[13] = cmul(b[13], W3);
    b[14] = cmul(b[14], W6);
    b[15] = cmul(b[15], W9);
#pragma unroll
    for (int k1 = 0; k1 < 4; ++k1) {
        float2 x0 = b[k1], x1 = b[4 + k1], x2 = b[8 + k1], x3 = b[12 + k1];
        float2 e = cadd(x0, x2), f = csub(x0, x2);
        float2 g = cadd(x1, x3), h = csub(x1, x3);
        a[k1 + 0]  = cadd(e, g);
        a[k1 + 4]  = cadd(f, cmul_negi(h));
        a[k1 + 8]  = csub(e, g);
        a[k1 + 12] = cadd(f, cmul_posi(h));
    }
}

// smem skew for stride-256 access patterns (+1 float2 per 256)
__device__ __forceinline__ unsigned swz(unsigned l) { return l + (l >> 8); }

// ---------------------------------------------------------------------------
// Radix-256 Stockham stage, mid form (complex in, direct store). s = 2^log2s.
// Block: 16 consecutive groups t = 16*bid + g, g = tid&15, j2 = tid>>4.
// Layer 1: DFT16 over j1 (in registers, data loaded directly in order),
//          twiddle w1^k1 with w1 = e^{-2pi i j2/256} * e^{-2pi i s p/N}.
// Transpose via smem.
// Layer 2: DFT16 over j2, twiddle w2^k2 with w2 = (e^{-2pi i s p/N})^16.
// Store y[q + 256 s p + s k1 + 16 s k2].
// ---------------------------------------------------------------------------
__global__ void fft256_mid(const float2* __restrict__ x, float2* __restrict__ y,
                           int log2s) {
    __shared__ float2 sm[4112];  // 4096 + 16 skew
    unsigned tid = threadIdx.x;
    unsigned g = tid & 15u, j2 = tid >> 4;
    unsigned t = blockIdx.x * 16u + g;
    unsigned s = 1u << log2s;
    unsigned q = t & (s - 1u);
    unsigned ps = t - q;  // p*s < 2^18, exact in float

    float2 a[16];
#pragma unroll
    for (int i = 0; i < 16; ++i) a[i] = x[t + (16u * (unsigned)i + j2) * N256];
    dft16(a);  // over j1 -> k1

    float sn, cs;
    __sincosf(-TWO_PI * (float)ps / (float)NFFT, &sn, &cs);
    float2 wg = make_float2(cs, sn);          // e^{-2pi i s p / N}
    float2 w1 = cmul(c_w256[j2], wg);
    float2 w = make_float2(1.f, 0.f);
#pragma unroll
    for (int k1 = 0; k1 < 16; ++k1) {
        sm[swz(tid + 256u * (unsigned)k1)] = cmul(a[k1], w);
        w = cmul(w, w1);
    }
    __syncthreads();

    unsigned k1p = tid >> 4;
#pragma unroll
    for (int j = 0; j < 16; ++j)
        a[j] = sm[swz(256u * k1p + 16u * (unsigned)j + g)];
    dft16(a);  // over j2 -> k2

    float2 w2 = cmul(wg, wg);
    w2 = cmul(w2, w2); w2 = cmul(w2, w2); w2 = cmul(w2, w2);  // wg^16
    unsigned base = q + (ps << 8) + (k1p << log2s);
    w = make_float2(1.f, 0.f);
#pragma unroll
    for (int k2 = 0; k2 < 16; ++k2) {
        y[base + ((unsigned)k2 << (log2s + 4))] = cmul(a[k2], w);
        w = cmul(w, w2);
    }
}

// ---------------------------------------------------------------------------
// P1: s = 1 (q = 0, p = t), real input; output restaged through smem so the
// block writes one contiguous 4096-element chunk y[4096*bid .. +4096).
// ---------------------------------------------------------------------------
__global__ void fft256_first(const float* __restrict__ x, float2* __restrict__ y) {
    __shared__ float2 sm[4112];
    unsigned tid = threadIdx.x;
    unsigned g = tid & 15u, j2 = tid >> 4;
    unsigned t = blockIdx.x * 16u + g;

    float2 a[16];
#pragma unroll
    for (int i = 0; i < 16; ++i)
        a[i] = make_float2(x[t + (16u * (unsigned)i + j2) * N256], 0.0f);
    dft16(a);

    float sn, cs;
    __sincosf(-TWO_PI * (float)t / (float)NFFT, &sn, &cs);
    float2 wg = make_float2(cs, sn);
    float2 w1 = cmul(c_w256[j2], wg);
    float2 w = make_float2(1.f, 0.f);
#pragma unroll
    for (int k1 = 0; k1 < 16; ++k1) {
        sm[swz(tid + 256u * (unsigned)k1)] = cmul(a[k1], w);
        w = cmul(w, w1);
    }
    __syncthreads();

    unsigned k1p = tid >> 4;
#pragma unroll
    for (int j = 0; j < 16; ++j)
        a[j] = sm[swz(256u * k1p + 16u * (unsigned)j + g)];
    dft16(a);

    float2 w2 = cmul(wg, wg);
    w2 = cmul(w2, w2); w2 = cmul(w2, w2); w2 = cmul(w2, w2);
    float2 r[16];
    w = make_float2(1.f, 0.f);
#pragma unroll
    for (int k2 = 0; k2 < 16; ++k2) { r[k2] = cmul(a[k2], w); w = cmul(w, w2); }

    __syncthreads();  // phase-2 reads done before restage overwrite
#pragma unroll
    for (int k2 = 0; k2 < 16; ++k2)
        sm[swz(256u * g + k1p + 16u * (unsigned)k2)] = r[k2];  // local idx 256g+k
    __syncthreads();

    unsigned base = blockIdx.x * 4096u;
#pragma unroll
    for (int i = 0; i < 16; ++i) {
        unsigned m = tid + 256u * (unsigned)i;
        y[base + m] = sm[swz(m)];
    }
}

// --------------- P4: radix-4, s = N/4, planar split store ---------------
__global__ void fft_p4_last(const float2* __restrict__ x, float* __restrict__ out) {
    unsigned t = blockIdx.x * TPB + threadIdx.x;
    float2 x0 = x[t];
    float2 x1 = x[t + N4];
    float2 x2 = x[t + 2 * N4];
    float2 x3 = x[t + 3 * N4];
    float2 e = cadd(x0, x2), f = csub(x0, x2);
    float2 g = cadd(x1, x3), h = csub(x1, x3);
    float2 r0 = cadd(e, g);
    float2 r1 = cadd(f, cmul_negi(h));
    float2 r2 = csub(e, g);
    float2 r3 = cadd(f, cmul_posi(h));
    out[t]          = r0.x;  out[NFFT + t]          = r0.y;
    out[t + N4]     = r1.x;  out[NFFT + t + N4]     = r1.y;
    out[t + 2 * N4] = r2.x;  out[NFFT + t + 2 * N4] = r2.y;
    out[t + 3 * N4] = r3.x;  out[NFFT + t + 3 * N4] = r3.y;
}

// ---------------------------------------------------------------------------
// Schedule: P1: x -> B; P2: B -> D (d_out as float2 scratch); P3: D -> B;
// P4: B -> d_out planar. P4 never reads d_out, so no aliasing hazard.
// ---------------------------------------------------------------------------
extern "C" void kernel_launch(void* const* d_in, const int* in_sizes, int n_in,
                              void* d_out, int out_size) {
    const float* x = (const float*)d_in[0];
    float* out = (float*)d_out;
    float2* D = (float2*)d_out;
    float2* B = nullptr;
    cudaGetSymbolAddress((void**)&B, g_buf);

    const unsigned blocks256 = N256 / 16u;  // 16384
    fft256_first<<<blocks256, TPB>>>(x, B);
    fft256_mid  <<<blocks256, TPB>>>(B, D, 8);
    fft256_mid  <<<blocks256, TPB>>>(D, B, 16);
    fft_p4_last <<<N4 / TPB, TPB>>>(B, out);
}